// round 2
// baseline (speedup 1.0000x reference)
#include <cuda_runtime.h>
#include <math.h>
#include <stdint.h>

// Problem-fixed max sizes (dataset is fixed: N=100000, E=1600000, EL=1000000)
#define NMAX 100000

// Scratch (device globals: allocation-free rule)
__device__ float g_deg [NMAX];
__device__ float g_dinv[NMAX];
__device__ float g_h   [NMAX * 64];
__device__ float g_hw  [NMAX * 64];
__device__ float g_out1[NMAX * 64];
__device__ float g_hw2 [NMAX * 32];
__device__ float g_z   [NMAX * 32];

// ---------------------------------------------------------------- degrees
__global__ void k_deg_init(int n) {
    int i = blockIdx.x * blockDim.x + threadIdx.x;
    if (i < n) g_deg[i] = 1.0f;   // self loop contributes 1
}

__global__ void k_deg_hist(const int* __restrict__ ei, int E) {
    int e = blockIdx.x * blockDim.x + threadIdx.x;
    if (e < E) atomicAdd(&g_deg[ei[E + e]], 1.0f);   // col = ei[1][e]
}

__global__ void k_dinv(int n) {
    int i = blockIdx.x * blockDim.x + threadIdx.x;
    if (i < n) g_dinv[i] = rsqrtf(g_deg[i]);
}

// ---------------------------------------------------------------- LSTM (gates i,g,o only; f gate is dead since c0=0)
// K-major weight tile, stride 192: bank(k*192+j) = j%32 -> conflict-free, no pad needed.
#define LSTM_WS 192

__global__ void k_lstm(const float* __restrict__ x,
                       const float* __restrict__ Wih,
                       const float* __restrict__ bih,
                       const float* __restrict__ bhh,
                       int N) {
    extern __shared__ float smem[];
    float* sW = smem;                    // [64][192] -> sW[k*192 + gi*64 + j]
    float* sb = sW + 64 * LSTM_WS;       // [192]
    float* sx = sb + 192;                // [8][64]
    int tid = threadIdx.x;

    // Stage W transposed: sW[k][gi*64+j] = Wih[(rowbase+j)*64 + k]; gates i,g,o -> row bases 0,128,192
    for (int idx = tid; idx < 64 * 192; idx += 256) {
        int k  = idx & 63;     // contiguous k per 64 consecutive tids -> coalesced global read
        int gj = idx >> 6;     // 0..191
        int gi = gj >> 6, j = gj & 63;
        int rb = (gi == 0) ? 0 : ((gi == 1) ? 128 : 192);
        sW[k * LSTM_WS + gj] = Wih[(rb + j) * 64 + k];
    }
    for (int idx = tid; idx < 192; idx += 256) {
        int gi = idx >> 6, j = idx & 63;
        int rb = (gi == 0) ? 0 : ((gi == 1) ? 128 : 192);
        sb[idx] = bih[rb + j] + bhh[rb + j];
    }
    __syncthreads();

    int j = tid & 63, slot = tid >> 6;   // 4 slots x 2 nodes = 8 nodes / iteration
    for (int base = blockIdx.x * 8; base < N; base += gridDim.x * 8) {
        __syncthreads();
        for (int idx = tid; idx < 512; idx += 256) {
            int n = base + (idx >> 6);
            sx[idx] = (n < N) ? x[(size_t)n * 64 + (idx & 63)] : 0.f;
        }
        __syncthreads();

        float ai = sb[j], ag = sb[64 + j], ao = sb[128 + j];
        float bi = ai, bg = ag, bo = ao;
        const float* x0 = &sx[slot * 128];
        const float* x1 = x0 + 64;
        #pragma unroll
        for (int k = 0; k < 64; k++) {
            float wi = sW[k * LSTM_WS + j];
            float wg = sW[k * LSTM_WS + 64 + j];
            float wo = sW[k * LSTM_WS + 128 + j];
            float v0 = x0[k], v1 = x1[k];
            ai += v0 * wi; ag += v0 * wg; ao += v0 * wo;
            bi += v1 * wi; bg += v1 * wg; bo += v1 * wo;
        }
        int n0 = base + slot * 2, n1 = n0 + 1;
        if (n0 < N) {
            float c = (1.f / (1.f + __expf(-ai))) * tanhf(ag);
            g_h[(size_t)n0 * 64 + j] = (1.f / (1.f + __expf(-ao))) * tanhf(c);
        }
        if (n1 < N) {
            float c = (1.f / (1.f + __expf(-bi))) * tanhf(bg);
            g_h[(size_t)n1 * 64 + j] = (1.f / (1.f + __expf(-bo))) * tanhf(c);
        }
    }
}

// ---------------------------------------------------------------- conv1 GEMM: hw = h@W1; out1 init = hw*dinv^2 + b1 (self loop + bias)
__global__ void k_gemm1(const float* __restrict__ W1, const float* __restrict__ b1, int N) {
    __shared__ float sW[64 * 64];
    __shared__ float sb[64];
    __shared__ float sx[8 * 64];
    int tid = threadIdx.x;
    for (int idx = tid; idx < 4096; idx += 256) sW[idx] = W1[idx];
    if (tid < 64) sb[tid] = b1[tid];
    __syncthreads();

    int j = tid & 63, slot = tid >> 6;
    for (int base = blockIdx.x * 8; base < N; base += gridDim.x * 8) {
        __syncthreads();
        for (int idx = tid; idx < 512; idx += 256) {
            int n = base + (idx >> 6);
            sx[idx] = (n < N) ? g_h[(size_t)n * 64 + (idx & 63)] : 0.f;
        }
        __syncthreads();
        float a0 = 0.f, a1 = 0.f;
        const float* x0 = &sx[slot * 128];
        const float* x1 = x0 + 64;
        #pragma unroll
        for (int k = 0; k < 64; k++) {
            float w = sW[k * 64 + j];
            a0 += x0[k] * w; a1 += x1[k] * w;
        }
        int n0 = base + slot * 2, n1 = n0 + 1;
        if (n0 < N) {
            g_hw[(size_t)n0 * 64 + j] = a0;
            float d = g_dinv[n0];
            g_out1[(size_t)n0 * 64 + j] = a0 * d * d + sb[j];
        }
        if (n1 < N) {
            g_hw[(size_t)n1 * 64 + j] = a1;
            float d = g_dinv[n1];
            g_out1[(size_t)n1 * 64 + j] = a1 * d * d + sb[j];
        }
    }
}

// ---------------------------------------------------------------- conv1 scatter: out1[col] += hw[row]*norm  (16 threads/edge, float4 + red.v4)
__global__ void k_scatter1(const int* __restrict__ ei, int E) {
    int t = blockIdx.x * blockDim.x + threadIdx.x;
    int e = t >> 4, c = t & 15;
    if (e >= E) return;
    int row = __ldg(&ei[e]);
    int col = __ldg(&ei[E + e]);
    float norm = __ldg(&g_dinv[row]) * __ldg(&g_dinv[col]);
    float4 v = *(const float4*)&g_hw[(size_t)row * 64 + c * 4];
    float* dst = &g_out1[(size_t)col * 64 + c * 4];
    asm volatile("red.global.add.v4.f32 [%0], {%1,%2,%3,%4};"
                 :: "l"(dst), "f"(v.x * norm), "f"(v.y * norm),
                    "f"(v.z * norm), "f"(v.w * norm) : "memory");
}

// ---------------------------------------------------------------- conv2 GEMM: hw2 = relu(out1)@W2; z init = hw2*dinv^2 + b2
__global__ void k_gemm2(const float* __restrict__ W2, const float* __restrict__ b2, int N) {
    __shared__ float sW[64 * 32];
    __shared__ float sb[32];
    __shared__ float sx[16 * 64];
    int tid = threadIdx.x;
    for (int idx = tid; idx < 2048; idx += 256) sW[idx] = W2[idx];
    if (tid < 32) sb[tid] = b2[tid];
    __syncthreads();

    int j = tid & 31, slot = tid >> 5;   // 8 slots x 2 nodes = 16 nodes / iter
    for (int base = blockIdx.x * 16; base < N; base += gridDim.x * 16) {
        __syncthreads();
        for (int idx = tid; idx < 1024; idx += 256) {
            int n = base + (idx >> 6);
            sx[idx] = (n < N) ? fmaxf(g_out1[(size_t)n * 64 + (idx & 63)], 0.f) : 0.f;
        }
        __syncthreads();
        float a0 = 0.f, a1 = 0.f;
        const float* x0 = &sx[slot * 128];
        const float* x1 = x0 + 64;
        #pragma unroll
        for (int k = 0; k < 64; k++) {
            float w = sW[k * 32 + j];
            a0 += x0[k] * w; a1 += x1[k] * w;
        }
        int n0 = base + slot * 2, n1 = n0 + 1;
        if (n0 < N) {
            g_hw2[(size_t)n0 * 32 + j] = a0;
            float d = g_dinv[n0];
            g_z[(size_t)n0 * 32 + j] = a0 * d * d + sb[j];
        }
        if (n1 < N) {
            g_hw2[(size_t)n1 * 32 + j] = a1;
            float d = g_dinv[n1];
            g_z[(size_t)n1 * 32 + j] = a1 * d * d + sb[j];
        }
    }
}

// ---------------------------------------------------------------- conv2 scatter (8 threads/edge)
__global__ void k_scatter2(const int* __restrict__ ei, int E) {
    int t = blockIdx.x * blockDim.x + threadIdx.x;
    int e = t >> 3, c = t & 7;
    if (e >= E) return;
    int row = __ldg(&ei[e]);
    int col = __ldg(&ei[E + e]);
    float norm = __ldg(&g_dinv[row]) * __ldg(&g_dinv[col]);
    float4 v = *(const float4*)&g_hw2[(size_t)row * 32 + c * 4];
    float* dst = &g_z[(size_t)col * 32 + c * 4];
    asm volatile("red.global.add.v4.f32 [%0], {%1,%2,%3,%4};"
                 :: "l"(dst), "f"(v.x * norm), "f"(v.y * norm),
                    "f"(v.z * norm), "f"(v.w * norm) : "memory");
}

// ---------------------------------------------------------------- label-edge dot: out[e] = z[src].z[dst]  (8 threads/edge)
__global__ void k_dot(const int* __restrict__ eli, float* __restrict__ out, int EL) {
    int t = blockIdx.x * blockDim.x + threadIdx.x;
    int e = t >> 3, c = t & 7;
    if (e >= EL) return;
    int s = __ldg(&eli[e]);
    int d = __ldg(&eli[EL + e]);
    float4 a = *(const float4*)&g_z[(size_t)s * 32 + c * 4];
    float4 b = *(const float4*)&g_z[(size_t)d * 32 + c * 4];
    float p = a.x * b.x + a.y * b.y + a.z * b.z + a.w * b.w;
    p += __shfl_down_sync(0xffffffffu, p, 4, 8);
    p += __shfl_down_sync(0xffffffffu, p, 2, 8);
    p += __shfl_down_sync(0xffffffffu, p, 1, 8);
    if (c == 0) out[e] = p;
}

// ---------------------------------------------------------------- launch
extern "C" void kernel_launch(void* const* d_in, const int* in_sizes, int n_in,
                              void* d_out, int out_size) {
    const float* x   = (const float*)d_in[0];
    const int*   ei  = (const int*)  d_in[1];
    const int*   eli = (const int*)  d_in[2];
    const float* Wih = (const float*)d_in[3];
    // d_in[4] = W_hh: unused (h0 == 0 => W_hh @ h0 == 0)
    const float* bih = (const float*)d_in[5];
    const float* bhh = (const float*)d_in[6];
    const float* W1  = (const float*)d_in[7];
    const float* b1  = (const float*)d_in[8];
    const float* W2  = (const float*)d_in[9];
    const float* b2  = (const float*)d_in[10];
    float* out = (float*)d_out;

    int N  = in_sizes[0] / 64;
    int E  = in_sizes[1] / 2;
    int EL = in_sizes[2] / 2;

    const int LSTM_SMEM = (64 * LSTM_WS + 192 + 512) * 4;  // 51968 B
    cudaFuncSetAttribute(k_lstm, cudaFuncAttributeMaxDynamicSharedMemorySize, LSTM_SMEM);
    (void)cudaGetLastError();  // never poison the capture stream with a sticky attr error

    int nb = (N + 255) / 256;
    k_deg_init<<<nb, 256>>>(N);
    k_deg_hist<<<(E + 255) / 256, 256>>>(ei, E);
    k_dinv<<<nb, 256>>>(N);
    k_lstm<<<592, 256, LSTM_SMEM>>>(x, Wih, bih, bhh, N);
    k_gemm1<<<1184, 256>>>(W1, b1, N);
    k_scatter1<<<(E * 16 + 255) / 256, 256>>>(ei, E);
    k_gemm2<<<1184, 256>>>(W2, b2, N);
    k_scatter2<<<(E * 8 + 255) / 256, 256>>>(ei, E);
    k_dot<<<(EL * 8 + 255) / 256, 256>>>(eli, out, EL);
}

// round 5
// speedup vs baseline: 1.1048x; 1.1048x over previous
#include <cuda_runtime.h>
#include <math.h>
#include <stdint.h>

// Problem-fixed max sizes (dataset is fixed: N=100000, E=1600000, EL=1000000)
#define NMAX 100000

// Scratch (device globals: allocation-free rule)
__device__ float g_deg [NMAX];
__device__ float g_dinv[NMAX];
__device__ float g_h   [NMAX * 64];
__device__ float g_hw  [NMAX * 64];
__device__ float g_out1[NMAX * 64];
__device__ float g_hw2 [NMAX * 32];
__device__ float g_z   [NMAX * 32];

// ---------------------------------------------------------------- degrees
__global__ void k_deg_init(int n) {
    int i = blockIdx.x * blockDim.x + threadIdx.x;
    if (i < n) g_deg[i] = 1.0f;   // self loop contributes 1
}

__global__ void k_deg_hist(const int* __restrict__ ei, int E) {
    int e = blockIdx.x * blockDim.x + threadIdx.x;
    if (e < E) atomicAdd(&g_deg[ei[E + e]], 1.0f);   // col = ei[1][e]
}

__global__ void k_dinv(int n) {
    int i = blockIdx.x * blockDim.x + threadIdx.x;
    if (i < n) g_dinv[i] = rsqrtf(g_deg[i]);
}

// ---------------------------------------------------------------- LSTM (gates i,g,o only; f gate dead since c0=0)
// Register-blocked: 4 nodes per weight load, k-unrolled by 4 with float4 x broadcasts.
#define LSTM_WS 192

__global__ void k_lstm(const float* __restrict__ x,
                       const float* __restrict__ Wih,
                       const float* __restrict__ bih,
                       const float* __restrict__ bhh,
                       int N) {
    extern __shared__ float smem[];
    float* sW = smem;                    // [64][192]: sW[k*192 + gi*64 + j]
    float* sb = sW + 64 * LSTM_WS;       // [192]
    float* sx = sb + 192;                // [16][64]
    int tid = threadIdx.x;

    // Stage W transposed: sW[k][gi*64+j] = Wih[(rowbase+j)*64 + k]; gates i,g,o -> rows 0,128,192
    for (int idx = tid; idx < 64 * 192; idx += 256) {
        int k  = idx & 63;
        int gj = idx >> 6;
        int gi = gj >> 6, j = gj & 63;
        int rb = (gi == 0) ? 0 : ((gi == 1) ? 128 : 192);
        sW[k * LSTM_WS + gj] = Wih[(rb + j) * 64 + k];
    }
    for (int idx = tid; idx < 192; idx += 256) {
        int gi = idx >> 6, j = idx & 63;
        int rb = (gi == 0) ? 0 : ((gi == 1) ? 128 : 192);
        sb[idx] = bih[rb + j] + bhh[rb + j];
    }
    __syncthreads();

    int j = tid & 63, slot = tid >> 6;   // 4 slots x 4 nodes = 16 nodes / iteration
    for (int base = blockIdx.x * 16; base < N; base += gridDim.x * 16) {
        __syncthreads();
        for (int idx = tid; idx < 1024; idx += 256) {
            int n = base + (idx >> 6);
            sx[idx] = (n < N) ? x[(size_t)n * 64 + (idx & 63)] : 0.f;
        }
        __syncthreads();

        float aI0 = sb[j],       aI1 = aI0, aI2 = aI0, aI3 = aI0;
        float aG0 = sb[64 + j],  aG1 = aG0, aG2 = aG0, aG3 = aG0;
        float aO0 = sb[128 + j], aO1 = aO0, aO2 = aO0, aO3 = aO0;
        const float* xs = &sx[slot * 256];

        #pragma unroll
        for (int k = 0; k < 64; k += 4) {
            float4 x0 = *(const float4*)&xs[k];
            float4 x1 = *(const float4*)&xs[64 + k];
            float4 x2 = *(const float4*)&xs[128 + k];
            float4 x3 = *(const float4*)&xs[192 + k];
            #pragma unroll
            for (int kk = 0; kk < 4; kk++) {
                float wi = sW[(k + kk) * LSTM_WS + j];
                float wg = sW[(k + kk) * LSTM_WS + 64 + j];
                float wo = sW[(k + kk) * LSTM_WS + 128 + j];
                float v0 = (&x0.x)[kk], v1 = (&x1.x)[kk];
                float v2 = (&x2.x)[kk], v3 = (&x3.x)[kk];
                aI0 += v0 * wi; aG0 += v0 * wg; aO0 += v0 * wo;
                aI1 += v1 * wi; aG1 += v1 * wg; aO1 += v1 * wo;
                aI2 += v2 * wi; aG2 += v2 * wg; aO2 += v2 * wo;
                aI3 += v3 * wi; aG3 += v3 * wg; aO3 += v3 * wo;
            }
        }

        int n0 = base + slot * 4;
        #pragma unroll
        for (int q = 0; q < 4; q++) {
            float ai = (q == 0) ? aI0 : (q == 1) ? aI1 : (q == 2) ? aI2 : aI3;
            float ag = (q == 0) ? aG0 : (q == 1) ? aG1 : (q == 2) ? aG2 : aG3;
            float ao = (q == 0) ? aO0 : (q == 1) ? aO1 : (q == 2) ? aO2 : aO3;
            int n = n0 + q;
            if (n < N) {
                float c = (1.f / (1.f + __expf(-ai))) * tanhf(ag);
                g_h[(size_t)n * 64 + j] = (1.f / (1.f + __expf(-ao))) * tanhf(c);
            }
        }
    }
}

// ---------------------------------------------------------------- conv1 GEMM: hw = h@W1; out1 init = hw*dinv^2 + b1
__global__ void k_gemm1(const float* __restrict__ W1, const float* __restrict__ b1, int N) {
    __shared__ float sW[64 * 64];
    __shared__ float sb[64];
    __shared__ float sx[16 * 64];
    int tid = threadIdx.x;
    for (int idx = tid; idx < 4096; idx += 256) sW[idx] = W1[idx];
    if (tid < 64) sb[tid] = b1[tid];
    __syncthreads();

    int j = tid & 63, slot = tid >> 6;   // 4 slots x 4 nodes = 16 nodes / iter
    for (int base = blockIdx.x * 16; base < N; base += gridDim.x * 16) {
        __syncthreads();
        for (int idx = tid; idx < 1024; idx += 256) {
            int n = base + (idx >> 6);
            sx[idx] = (n < N) ? g_h[(size_t)n * 64 + (idx & 63)] : 0.f;
        }
        __syncthreads();
        float a0 = 0.f, a1 = 0.f, a2 = 0.f, a3 = 0.f;
        const float* xs = &sx[slot * 256];
        #pragma unroll
        for (int k = 0; k < 64; k += 4) {
            float4 x0 = *(const float4*)&xs[k];
            float4 x1 = *(const float4*)&xs[64 + k];
            float4 x2 = *(const float4*)&xs[128 + k];
            float4 x3 = *(const float4*)&xs[192 + k];
            #pragma unroll
            for (int kk = 0; kk < 4; kk++) {
                float w = sW[(k + kk) * 64 + j];
                a0 += (&x0.x)[kk] * w;
                a1 += (&x1.x)[kk] * w;
                a2 += (&x2.x)[kk] * w;
                a3 += (&x3.x)[kk] * w;
            }
        }
        int n0 = base + slot * 4;
        #pragma unroll
        for (int q = 0; q < 4; q++) {
            float a = (q == 0) ? a0 : (q == 1) ? a1 : (q == 2) ? a2 : a3;
            int n = n0 + q;
            if (n < N) {
                g_hw[(size_t)n * 64 + j] = a;
                float d = g_dinv[n];
                g_out1[(size_t)n * 64 + j] = a * d * d + sb[j];
            }
        }
    }
}

// ---------------------------------------------------------------- conv1 scatter: out1[col] += hw[row]*norm
__global__ void k_scatter1(const int* __restrict__ ei, int E) {
    int t = blockIdx.x * blockDim.x + threadIdx.x;
    int e = t >> 4, c = t & 15;
    if (e >= E) return;
    int row = __ldg(&ei[e]);
    int col = __ldg(&ei[E + e]);
    float norm = __ldg(&g_dinv[row]) * __ldg(&g_dinv[col]);
    float4 v = *(const float4*)&g_hw[(size_t)row * 64 + c * 4];
    float* dst = &g_out1[(size_t)col * 64 + c * 4];
    asm volatile("red.global.add.v4.f32 [%0], {%1,%2,%3,%4};"
                 :: "l"(dst), "f"(v.x * norm), "f"(v.y * norm),
                    "f"(v.z * norm), "f"(v.w * norm) : "memory");
}

// ---------------------------------------------------------------- conv2 GEMM: hw2 = relu(out1)@W2; z init = hw2*dinv^2 + b2
__global__ void k_gemm2(const float* __restrict__ W2, const float* __restrict__ b2, int N) {
    __shared__ float sW[64 * 32];
    __shared__ float sb[32];
    __shared__ float sx[32 * 64];
    int tid = threadIdx.x;
    for (int idx = tid; idx < 2048; idx += 256) sW[idx] = W2[idx];
    if (tid < 32) sb[tid] = b2[tid];
    __syncthreads();

    int j = tid & 31, slot = tid >> 5;   // 8 slots x 4 nodes = 32 nodes / iter
    for (int base = blockIdx.x * 32; base < N; base += gridDim.x * 32) {
        __syncthreads();
        for (int idx = tid; idx < 2048; idx += 256) {
            int n = base + (idx >> 6);
            sx[idx] = (n < N) ? fmaxf(g_out1[(size_t)n * 64 + (idx & 63)], 0.f) : 0.f;
        }
        __syncthreads();
        float a0 = 0.f, a1 = 0.f, a2 = 0.f, a3 = 0.f;
        const float* xs = &sx[slot * 256];
        #pragma unroll
        for (int k = 0; k < 64; k += 4) {
            float4 x0 = *(const float4*)&xs[k];
            float4 x1 = *(const float4*)&xs[64 + k];
            float4 x2 = *(const float4*)&xs[128 + k];
            float4 x3 = *(const float4*)&xs[192 + k];
            #pragma unroll
            for (int kk = 0; kk < 4; kk++) {
                float w = sW[(k + kk) * 32 + j];
                a0 += (&x0.x)[kk] * w;
                a1 += (&x1.x)[kk] * w;
                a2 += (&x2.x)[kk] * w;
                a3 += (&x3.x)[kk] * w;
            }
        }
        int n0 = base + slot * 4;
        #pragma unroll
        for (int q = 0; q < 4; q++) {
            float a = (q == 0) ? a0 : (q == 1) ? a1 : (q == 2) ? a2 : a3;
            int n = n0 + q;
            if (n < N) {
                g_hw2[(size_t)n * 32 + j] = a;
                float d = g_dinv[n];
                g_z[(size_t)n * 32 + j] = a * d * d + sb[j];
            }
        }
    }
}

// ---------------------------------------------------------------- conv2 scatter (8 threads/edge)
__global__ void k_scatter2(const int* __restrict__ ei, int E) {
    int t = blockIdx.x * blockDim.x + threadIdx.x;
    int e = t >> 3, c = t & 7;
    if (e >= E) return;
    int row = __ldg(&ei[e]);
    int col = __ldg(&ei[E + e]);
    float norm = __ldg(&g_dinv[row]) * __ldg(&g_dinv[col]);
    float4 v = *(const float4*)&g_hw2[(size_t)row * 32 + c * 4];
    float* dst = &g_z[(size_t)col * 32 + c * 4];
    asm volatile("red.global.add.v4.f32 [%0], {%1,%2,%3,%4};"
                 :: "l"(dst), "f"(v.x * norm), "f"(v.y * norm),
                    "f"(v.z * norm), "f"(v.w * norm) : "memory");
}

// ---------------------------------------------------------------- label-edge dot (8 threads/edge)
__global__ void k_dot(const int* __restrict__ eli, float* __restrict__ out, int EL) {
    int t = blockIdx.x * blockDim.x + threadIdx.x;
    int e = t >> 3, c = t & 7;
    if (e >= EL) return;
    int s = __ldg(&eli[e]);
    int d = __ldg(&eli[EL + e]);
    float4 a = *(const float4*)&g_z[(size_t)s * 32 + c * 4];
    float4 b = *(const float4*)&g_z[(size_t)d * 32 + c * 4];
    float p = a.x * b.x + a.y * b.y + a.z * b.z + a.w * b.w;
    p += __shfl_down_sync(0xffffffffu, p, 4, 8);
    p += __shfl_down_sync(0xffffffffu, p, 2, 8);
    p += __shfl_down_sync(0xffffffffu, p, 1, 8);
    if (c == 0) out[e] = p;
}

// ---------------------------------------------------------------- launch
extern "C" void kernel_launch(void* const* d_in, const int* in_sizes, int n_in,
                              void* d_out, int out_size) {
    const float* x   = (const float*)d_in[0];
    const int*   ei  = (const int*)  d_in[1];
    const int*   eli = (const int*)  d_in[2];
    const float* Wih = (const float*)d_in[3];
    // d_in[4] = W_hh: unused (h0 == 0 => W_hh @ h0 == 0)
    const float* bih = (const float*)d_in[5];
    const float* bhh = (const float*)d_in[6];
    const float* W1  = (const float*)d_in[7];
    const float* b1  = (const float*)d_in[8];
    const float* W2  = (const float*)d_in[9];
    const float* b2  = (const float*)d_in[10];
    float* out = (float*)d_out;

    int N  = in_sizes[0] / 64;
    int E  = in_sizes[1] / 2;
    int EL = in_sizes[2] / 2;

    const int LSTM_SMEM = (64 * LSTM_WS + 192 + 1024) * 4;  // 54016 B
    cudaFuncSetAttribute(k_lstm, cudaFuncAttributeMaxDynamicSharedMemorySize, LSTM_SMEM);
    (void)cudaGetLastError();  // never poison the capture stream

    int nb = (N + 255) / 256;
    k_deg_init<<<nb, 256>>>(N);
    k_deg_hist<<<(E + 255) / 256, 256>>>(ei, E);
    k_dinv<<<nb, 256>>>(N);
    k_lstm<<<592, 256, LSTM_SMEM>>>(x, Wih, bih, bhh, N);
    k_gemm1<<<1184, 256>>>(W1, b1, N);
    k_scatter1<<<(E * 16 + 255) / 256, 256>>>(ei, E);
    k_gemm2<<<1184, 256>>>(W2, b2, N);
    k_scatter2<<<(E * 8 + 255) / 256, 256>>>(ei, E);
    k_dot<<<(EL * 8 + 255) / 256, 256>>>(eli, out, EL);
}

// round 6
// speedup vs baseline: 1.4634x; 1.3245x over previous
#include <cuda_runtime.h>
#include <math.h>
#include <stdint.h>

// Problem-fixed sizes (dataset is fixed: N=100000, E=1600000, EL=1000000)
#define NMAX 100000
#define EMAX 1600000

// Scratch (device globals: allocation-free rule)
__device__ float g_dinv [NMAX];
__device__ int   g_cnt  [NMAX];      // in-edge count per col (no self loop)
__device__ int   g_start[NMAX];      // CSR exclusive start
__device__ int   g_cur  [NMAX];      // fill cursor
__device__ int   g_bsum [128];       // scan block sums (98 used)
__device__ int   g_elist[EMAX];      // CSR edge list: row indices grouped by col
__device__ float g_h    [NMAX * 64];
__device__ float g_hw   [NMAX * 64]; // dinv[n] * (h @ W1)
__device__ float g_out1 [NMAX * 64]; // relu(conv1 out)
__device__ float g_hw2  [NMAX * 32]; // dinv[n] * (out1 @ W2)
__device__ float g_z    [NMAX * 32];

// ---------------------------------------------------------------- CSR build
__global__ void k_zero(int n) {
    int i = blockIdx.x * blockDim.x + threadIdx.x;
    if (i < n) { g_cnt[i] = 0; g_cur[i] = 0; }
}

__global__ void k_hist(const int* __restrict__ ei, int E) {
    int e = blockIdx.x * blockDim.x + threadIdx.x;
    if (e < E) atomicAdd(&g_cnt[ei[E + e]], 1);   // col = ei[1][e]
}

__global__ void k_dinv(int n) {
    int i = blockIdx.x * blockDim.x + threadIdx.x;
    if (i < n) g_dinv[i] = rsqrtf((float)(g_cnt[i] + 1));   // +1 self loop
}

// scan over g_cnt -> g_start (exclusive). 1024 elems per 256-thread block.
__global__ void k_scan1(int n) {
    __shared__ int wsum[8];
    int tid = threadIdx.x;
    int base = blockIdx.x * 1024 + tid * 4;
    int v0 = (base     < n) ? g_cnt[base]     : 0;
    int v1 = (base + 1 < n) ? g_cnt[base + 1] : 0;
    int v2 = (base + 2 < n) ? g_cnt[base + 2] : 0;
    int v3 = (base + 3 < n) ? g_cnt[base + 3] : 0;
    int t = v0 + v1 + v2 + v3;
    int lane = tid & 31, wid = tid >> 5;
    int s = t;
    #pragma unroll
    for (int o = 1; o < 32; o <<= 1) {
        int u = __shfl_up_sync(0xffffffffu, s, o);
        if (lane >= o) s += u;
    }
    if (lane == 31) wsum[wid] = s;
    __syncthreads();
    if (tid == 0) {
        int acc = 0;
        for (int w = 0; w < 8; w++) { int x = wsum[w]; wsum[w] = acc; acc += x; }
        g_bsum[blockIdx.x] = acc;
    }
    __syncthreads();
    int excl = s - t + wsum[wid];
    if (base     < n) g_start[base]     = excl;
    if (base + 1 < n) g_start[base + 1] = excl + v0;
    if (base + 2 < n) g_start[base + 2] = excl + v0 + v1;
    if (base + 3 < n) g_start[base + 3] = excl + v0 + v1 + v2;
}

__global__ void k_scan2(int nb) {
    if (threadIdx.x == 0 && blockIdx.x == 0) {
        int acc = 0;
        for (int b = 0; b < nb; b++) { int x = g_bsum[b]; g_bsum[b] = acc; acc += x; }
    }
}

__global__ void k_scan3(int n) {
    int i = blockIdx.x * blockDim.x + threadIdx.x;
    if (i < n) g_start[i] += g_bsum[i >> 10];
}

__global__ void k_fill(const int* __restrict__ ei, int E) {
    int e = blockIdx.x * blockDim.x + threadIdx.x;
    if (e >= E) return;
    int row = ei[e];
    int col = ei[E + e];
    int pos = atomicAdd(&g_cur[col], 1);
    g_elist[g_start[col] + pos] = row;
}

// ---------------------------------------------------------------- LSTM (gates i,g,o; f gate dead since c0=0)
// 8 nodes per weight load, k-unroll 4: per 4k -> 8 LDS.128 + 12 LDS + 96 FFMA (83% FMA).
#define LSTM_WS 192

__global__ void k_lstm(const float* __restrict__ x,
                       const float* __restrict__ Wih,
                       const float* __restrict__ bih,
                       const float* __restrict__ bhh,
                       int N) {
    extern __shared__ float smem[];
    float* sW = smem;                    // [64][192]: sW[k*192 + gi*64 + j]
    float* sb = sW + 64 * LSTM_WS;       // [192]
    float* sx = sb + 192;                // [32][64]
    int tid = threadIdx.x;

    for (int idx = tid; idx < 64 * 192; idx += 256) {
        int k  = idx & 63;
        int gj = idx >> 6;
        int gi = gj >> 6, j = gj & 63;
        int rb = (gi == 0) ? 0 : ((gi == 1) ? 128 : 192);
        sW[k * LSTM_WS + gj] = Wih[(rb + j) * 64 + k];
    }
    for (int idx = tid; idx < 192; idx += 256) {
        int gi = idx >> 6, j = idx & 63;
        int rb = (gi == 0) ? 0 : ((gi == 1) ? 128 : 192);
        sb[idx] = bih[rb + j] + bhh[rb + j];
    }
    __syncthreads();

    int j = tid & 63, slot = tid >> 6;   // 4 slots x 8 nodes = 32 nodes / iteration
    for (int base = blockIdx.x * 32; base < N; base += gridDim.x * 32) {
        __syncthreads();
        for (int idx = tid; idx < 2048; idx += 256) {
            int n = base + (idx >> 6);
            sx[idx] = (n < N) ? x[(size_t)n * 64 + (idx & 63)] : 0.f;
        }
        __syncthreads();

        float aI[8], aG[8], aO[8];
        #pragma unroll
        for (int r = 0; r < 8; r++) { aI[r] = sb[j]; aG[r] = sb[64 + j]; aO[r] = sb[128 + j]; }
        const float* xs = &sx[slot * 512];

        #pragma unroll
        for (int k = 0; k < 64; k += 4) {
            float4 xv[8];
            #pragma unroll
            for (int r = 0; r < 8; r++) xv[r] = *(const float4*)&xs[r * 64 + k];
            #pragma unroll
            for (int kk = 0; kk < 4; kk++) {
                float wi = sW[(k + kk) * LSTM_WS + j];
                float wg = sW[(k + kk) * LSTM_WS + 64 + j];
                float wo = sW[(k + kk) * LSTM_WS + 128 + j];
                #pragma unroll
                for (int r = 0; r < 8; r++) {
                    float v = (&xv[r].x)[kk];
                    aI[r] += v * wi; aG[r] += v * wg; aO[r] += v * wo;
                }
            }
        }

        int n0 = base + slot * 8;
        #pragma unroll
        for (int r = 0; r < 8; r++) {
            int n = n0 + r;
            if (n < N) {
                float c = (1.f / (1.f + __expf(-aI[r]))) * tanhf(aG[r]);
                g_h[(size_t)n * 64 + j] = (1.f / (1.f + __expf(-aO[r]))) * tanhf(c);
            }
        }
    }
}

// ---------------------------------------------------------------- conv1 GEMM: g_hw = dinv[n] * (h @ W1)
__global__ void k_gemm1(const float* __restrict__ W1, int N) {
    __shared__ float sW[64 * 64];
    __shared__ float sx[32 * 64];
    int tid = threadIdx.x;
    for (int idx = tid; idx < 4096; idx += 256) sW[idx] = W1[idx];
    __syncthreads();

    int j = tid & 63, slot = tid >> 6;   // 4 slots x 8 nodes = 32 / iter
    for (int base = blockIdx.x * 32; base < N; base += gridDim.x * 32) {
        __syncthreads();
        for (int idx = tid; idx < 2048; idx += 256) {
            int n = base + (idx >> 6);
            sx[idx] = (n < N) ? g_h[(size_t)n * 64 + (idx & 63)] : 0.f;
        }
        __syncthreads();
        float a[8];
        #pragma unroll
        for (int r = 0; r < 8; r++) a[r] = 0.f;
        const float* xs = &sx[slot * 512];
        #pragma unroll
        for (int k = 0; k < 64; k += 4) {
            float4 xv[8];
            #pragma unroll
            for (int r = 0; r < 8; r++) xv[r] = *(const float4*)&xs[r * 64 + k];
            #pragma unroll
            for (int kk = 0; kk < 4; kk++) {
                float w = sW[(k + kk) * 64 + j];
                #pragma unroll
                for (int r = 0; r < 8; r++) a[r] += (&xv[r].x)[kk] * w;
            }
        }
        int n0 = base + slot * 8;
        #pragma unroll
        for (int r = 0; r < 8; r++) {
            int n = n0 + r;
            if (n < N) g_hw[(size_t)n * 64 + j] = a[r] * g_dinv[n];
        }
    }
}

// ---------------------------------------------------------------- conv1 gather: out1[c] = relu(dinv[c]*(hws[c] + sum_in hws[r]) + b1)
__global__ void k_gather1(const float* __restrict__ b1, int N) {
    int g = blockIdx.x * blockDim.x + threadIdx.x;
    int c = g >> 4, ln = g & 15;
    if (c >= N) return;
    int s = g_start[c], cnt = g_cnt[c];
    float4 acc = *(const float4*)&g_hw[(size_t)c * 64 + ln * 4];   // self term
    int r = (cnt > 0) ? __ldg(&g_elist[s]) : 0;
    for (int i = 0; i < cnt; i++) {
        int rn = (i + 1 < cnt) ? __ldg(&g_elist[s + i + 1]) : 0;
        float4 v = *(const float4*)&g_hw[(size_t)r * 64 + ln * 4];
        acc.x += v.x; acc.y += v.y; acc.z += v.z; acc.w += v.w;
        r = rn;
    }
    float dc = g_dinv[c];
    float4 b = *(const float4*)&b1[ln * 4];
    float4 o;
    o.x = fmaxf(acc.x * dc + b.x, 0.f);
    o.y = fmaxf(acc.y * dc + b.y, 0.f);
    o.z = fmaxf(acc.z * dc + b.z, 0.f);
    o.w = fmaxf(acc.w * dc + b.w, 0.f);
    *(float4*)&g_out1[(size_t)c * 64 + ln * 4] = o;
}

// ---------------------------------------------------------------- conv2 GEMM: g_hw2 = dinv[n] * (out1 @ W2)
__global__ void k_gemm2(const float* __restrict__ W2, int N) {
    __shared__ float sW[64 * 32];
    __shared__ float sx[64 * 64];
    int tid = threadIdx.x;
    for (int idx = tid; idx < 2048; idx += 256) sW[idx] = W2[idx];
    __syncthreads();

    int j = tid & 31, slot = tid >> 5;   // 8 slots x 8 nodes = 64 / iter
    for (int base = blockIdx.x * 64; base < N; base += gridDim.x * 64) {
        __syncthreads();
        for (int idx = tid; idx < 4096; idx += 256) {
            int n = base + (idx >> 6);
            sx[idx] = (n < N) ? g_out1[(size_t)n * 64 + (idx & 63)] : 0.f;
        }
        __syncthreads();
        float a[8];
        #pragma unroll
        for (int r = 0; r < 8; r++) a[r] = 0.f;
        const float* xs = &sx[slot * 512];
        #pragma unroll
        for (int k = 0; k < 64; k += 4) {
            float4 xv[8];
            #pragma unroll
            for (int r = 0; r < 8; r++) xv[r] = *(const float4*)&xs[r * 64 + k];
            #pragma unroll
            for (int kk = 0; kk < 4; kk++) {
                float w = sW[(k + kk) * 32 + j];
                #pragma unroll
                for (int r = 0; r < 8; r++) a[r] += (&xv[r].x)[kk] * w;
            }
        }
        int n0 = base + slot * 8;
        #pragma unroll
        for (int r = 0; r < 8; r++) {
            int n = n0 + r;
            if (n < N) g_hw2[(size_t)n * 32 + j] = a[r] * g_dinv[n];
        }
    }
}

// ---------------------------------------------------------------- conv2 gather: z[c] = dinv[c]*(hw2s[c] + sum) + b2
__global__ void k_gather2(const float* __restrict__ b2, int N) {
    int g = blockIdx.x * blockDim.x + threadIdx.x;
    int c = g >> 3, ln = g & 7;
    if (c >= N) return;
    int s = g_start[c], cnt = g_cnt[c];
    float4 acc = *(const float4*)&g_hw2[(size_t)c * 32 + ln * 4];  // self term
    int r = (cnt > 0) ? __ldg(&g_elist[s]) : 0;
    for (int i = 0; i < cnt; i++) {
        int rn = (i + 1 < cnt) ? __ldg(&g_elist[s + i + 1]) : 0;
        float4 v = *(const float4*)&g_hw2[(size_t)r * 32 + ln * 4];
        acc.x += v.x; acc.y += v.y; acc.z += v.z; acc.w += v.w;
        r = rn;
    }
    float dc = g_dinv[c];
    float4 b = *(const float4*)&b2[ln * 4];
    float4 o;
    o.x = acc.x * dc + b.x;
    o.y = acc.y * dc + b.y;
    o.z = acc.z * dc + b.z;
    o.w = acc.w * dc + b.w;
    *(float4*)&g_z[(size_t)c * 32 + ln * 4] = o;
}

// ---------------------------------------------------------------- label-edge dot (8 threads/edge)
__global__ void k_dot(const int* __restrict__ eli, float* __restrict__ out, int EL) {
    int t = blockIdx.x * blockDim.x + threadIdx.x;
    int e = t >> 3, c = t & 7;
    if (e >= EL) return;
    int s = __ldg(&eli[e]);
    int d = __ldg(&eli[EL + e]);
    float4 a = *(const float4*)&g_z[(size_t)s * 32 + c * 4];
    float4 b = *(const float4*)&g_z[(size_t)d * 32 + c * 4];
    float p = a.x * b.x + a.y * b.y + a.z * b.z + a.w * b.w;
    p += __shfl_down_sync(0xffffffffu, p, 4, 8);
    p += __shfl_down_sync(0xffffffffu, p, 2, 8);
    p += __shfl_down_sync(0xffffffffu, p, 1, 8);
    if (c == 0) out[e] = p;
}

// ---------------------------------------------------------------- launch
extern "C" void kernel_launch(void* const* d_in, const int* in_sizes, int n_in,
                              void* d_out, int out_size) {
    const float* x   = (const float*)d_in[0];
    const int*   ei  = (const int*)  d_in[1];
    const int*   eli = (const int*)  d_in[2];
    const float* Wih = (const float*)d_in[3];
    // d_in[4] = W_hh: unused (h0 == 0 => W_hh @ h0 == 0)
    const float* bih = (const float*)d_in[5];
    const float* bhh = (const float*)d_in[6];
    const float* W1  = (const float*)d_in[7];
    const float* b1  = (const float*)d_in[8];
    const float* W2  = (const float*)d_in[9];
    const float* b2  = (const float*)d_in[10];
    float* out = (float*)d_out;

    int N  = in_sizes[0] / 64;
    int E  = in_sizes[1] / 2;
    int EL = in_sizes[2] / 2;

    const int LSTM_SMEM = (64 * LSTM_WS + 192 + 2048) * 4;  // 58112 B
    cudaFuncSetAttribute(k_lstm, cudaFuncAttributeMaxDynamicSharedMemorySize, LSTM_SMEM);
    (void)cudaGetLastError();  // never poison the capture stream

    int nb    = (N + 255) / 256;
    int nscan = (N + 1023) / 1024;

    // CSR build + norms
    k_zero <<<nb, 256>>>(N);
    k_hist <<<(E + 255) / 256, 256>>>(ei, E);
    k_dinv <<<nb, 256>>>(N);
    k_scan1<<<nscan, 256>>>(N);
    k_scan2<<<1, 32>>>(nscan);
    k_scan3<<<nb, 256>>>(N);
    k_fill <<<(E + 255) / 256, 256>>>(ei, E);

    // Pipeline
    k_lstm   <<<444, 256, LSTM_SMEM>>>(x, Wih, bih, bhh, N);
    k_gemm1  <<<592, 256>>>(W1, N);
    k_gather1<<<(N * 16 + 255) / 256, 256>>>(b1, N);
    k_gemm2  <<<592, 256>>>(W2, N);
    k_gather2<<<(N * 8 + 255) / 256, 256>>>(b2, N);
    k_dot    <<<(EL * 8 + 255) / 256, 256>>>(eli, out, EL);
}

// round 8
// speedup vs baseline: 1.4932x; 1.0204x over previous
#include <cuda_runtime.h>
#include <math.h>
#include <stdint.h>

// Problem-fixed sizes (dataset is fixed: N=100000, E=1600000, EL=1000000)
#define NMAX 100000
#define EMAX 1600000

// Scratch (device globals: allocation-free rule)
__device__ float g_dinv [NMAX];
__device__ int   g_cnt  [NMAX];      // in-edge count per col (no self loop)
__device__ int   g_start[NMAX];      // CSR exclusive start
__device__ int   g_cur  [NMAX];      // fill cursor (initialized to start)
__device__ int   g_bsum [128];       // scan block sums (98 used)
__device__ int   g_elist[EMAX];      // CSR edge list: row indices grouped by col
__device__ float g_h    [NMAX * 64];
__device__ float g_hw   [NMAX * 64]; // dinv[n] * (h @ W1)
__device__ float g_hw2  [NMAX * 32]; // dinv[n] * (out1 @ W2)
__device__ float g_z    [NMAX * 32];

// ---------------------------------------------------------------- CSR build (5 launches)
__global__ void k_zero(int n) {
    int i = blockIdx.x * blockDim.x + threadIdx.x;
    if (i < n) g_cnt[i] = 0;
}

__global__ void k_hist(const int* __restrict__ ei, int E) {
    int e = blockIdx.x * blockDim.x + threadIdx.x;
    if (e < E) atomicAdd(&g_cnt[ei[E + e]], 1);   // col = ei[1][e]
}

// scan over g_cnt -> g_start (intra-block exclusive) + block totals + dinv.
// 1024 elems per 256-thread block.
__global__ void k_scan1(int n) {
    __shared__ int wsum[8];
    int tid = threadIdx.x;
    int base = blockIdx.x * 1024 + tid * 4;
    int v0 = (base     < n) ? g_cnt[base]     : 0;
    int v1 = (base + 1 < n) ? g_cnt[base + 1] : 0;
    int v2 = (base + 2 < n) ? g_cnt[base + 2] : 0;
    int v3 = (base + 3 < n) ? g_cnt[base + 3] : 0;
    // dinv fused here (cnt already in registers)
    if (base     < n) g_dinv[base]     = rsqrtf((float)(v0 + 1));
    if (base + 1 < n) g_dinv[base + 1] = rsqrtf((float)(v1 + 1));
    if (base + 2 < n) g_dinv[base + 2] = rsqrtf((float)(v2 + 1));
    if (base + 3 < n) g_dinv[base + 3] = rsqrtf((float)(v3 + 1));
    int t = v0 + v1 + v2 + v3;
    int lane = tid & 31, wid = tid >> 5;
    int s = t;
    #pragma unroll
    for (int o = 1; o < 32; o <<= 1) {
        int u = __shfl_up_sync(0xffffffffu, s, o);
        if (lane >= o) s += u;
    }
    if (lane == 31) wsum[wid] = s;
    __syncthreads();
    if (tid == 0) {
        int acc = 0;
        for (int w = 0; w < 8; w++) { int x = wsum[w]; wsum[w] = acc; acc += x; }
        g_bsum[blockIdx.x] = acc;
    }
    __syncthreads();
    int excl = s - t + wsum[wid];
    if (base     < n) g_start[base]     = excl;
    if (base + 1 < n) g_start[base + 1] = excl + v0;
    if (base + 2 < n) g_start[base + 2] = excl + v0 + v1;
    if (base + 3 < n) g_start[base + 3] = excl + v0 + v1 + v2;
}

// Per-block: compute prefix over g_bsum for this block's (single) scan segment,
// then finalize g_start and init g_cur. 256 indices/block -> one segment (idx>>10).
__global__ void k_scan3(int n) {
    __shared__ int sp[8];
    int tid = threadIdx.x;
    int seg = (int)(blockIdx.x >> 2);         // this block's 1024-wide scan segment
    int p = (tid < 128 && tid < seg) ? g_bsum[tid] : 0;   // seg <= 98 < 128
    #pragma unroll
    for (int o = 16; o > 0; o >>= 1) p += __shfl_down_sync(0xffffffffu, p, o);
    if ((tid & 31) == 0) sp[tid >> 5] = p;
    __syncthreads();
    if (tid == 0) sp[0] = sp[0] + sp[1] + sp[2] + sp[3];
    __syncthreads();
    int prefix = sp[0];
    int i = blockIdx.x * 256 + tid;
    if (i < n) {
        int st = g_start[i] + prefix;
        g_start[i] = st;
        g_cur[i]   = st;
    }
}

__global__ void k_fill(const int* __restrict__ ei, int E) {
    int e = blockIdx.x * blockDim.x + threadIdx.x;
    if (e >= E) return;
    int row = ei[e];
    int col = ei[E + e];
    int pos = atomicAdd(&g_cur[col], 1);
    g_elist[pos] = row;
}

// ---------------------------------------------------------------- LSTM (gates i,g,o; f gate dead since c0=0)
// 8 nodes per weight load, k-unroll 4.
#define LSTM_WS 192

__global__ void k_lstm(const float* __restrict__ x,
                       const float* __restrict__ Wih,
                       const float* __restrict__ bih,
                       const float* __restrict__ bhh,
                       int N) {
    extern __shared__ float smem[];
    float* sW = smem;                    // [64][192]: sW[k*192 + gi*64 + j]
    float* sb = sW + 64 * LSTM_WS;       // [192]
    float* sx = sb + 192;                // [32][64]
    int tid = threadIdx.x;

    for (int idx = tid; idx < 64 * 192; idx += 256) {
        int k  = idx & 63;
        int gj = idx >> 6;
        int gi = gj >> 6, j = gj & 63;
        int rb = (gi == 0) ? 0 : ((gi == 1) ? 128 : 192);
        sW[k * LSTM_WS + gj] = Wih[(rb + j) * 64 + k];
    }
    for (int idx = tid; idx < 192; idx += 256) {
        int gi = idx >> 6, j = idx & 63;
        int rb = (gi == 0) ? 0 : ((gi == 1) ? 128 : 192);
        sb[idx] = bih[rb + j] + bhh[rb + j];
    }
    __syncthreads();

    int j = tid & 63, slot = tid >> 6;   // 4 slots x 8 nodes = 32 nodes / iteration
    for (int base = blockIdx.x * 32; base < N; base += gridDim.x * 32) {
        __syncthreads();
        for (int idx = tid; idx < 2048; idx += 256) {
            int n = base + (idx >> 6);
            sx[idx] = (n < N) ? x[(size_t)n * 64 + (idx & 63)] : 0.f;
        }
        __syncthreads();

        float aI[8], aG[8], aO[8];
        #pragma unroll
        for (int r = 0; r < 8; r++) { aI[r] = sb[j]; aG[r] = sb[64 + j]; aO[r] = sb[128 + j]; }
        const float* xs = &sx[slot * 512];

        #pragma unroll
        for (int k = 0; k < 64; k += 4) {
            float4 xv[8];
            #pragma unroll
            for (int r = 0; r < 8; r++) xv[r] = *(const float4*)&xs[r * 64 + k];
            #pragma unroll
            for (int kk = 0; kk < 4; kk++) {
                float wi = sW[(k + kk) * LSTM_WS + j];
                float wg = sW[(k + kk) * LSTM_WS + 64 + j];
                float wo = sW[(k + kk) * LSTM_WS + 128 + j];
                #pragma unroll
                for (int r = 0; r < 8; r++) {
                    float v = (&xv[r].x)[kk];
                    aI[r] += v * wi; aG[r] += v * wg; aO[r] += v * wo;
                }
            }
        }

        int n0 = base + slot * 8;
        #pragma unroll
        for (int r = 0; r < 8; r++) {
            int n = n0 + r;
            if (n < N) {
                float c = (1.f / (1.f + __expf(-aI[r]))) * tanhf(aG[r]);
                g_h[(size_t)n * 64 + j] = (1.f / (1.f + __expf(-aO[r]))) * tanhf(c);
            }
        }
    }
}

// ---------------------------------------------------------------- conv1 GEMM: g_hw = dinv[n] * (h @ W1)
__global__ void k_gemm1(const float* __restrict__ W1, int N) {
    __shared__ float sW[64 * 64];
    __shared__ float sx[32 * 64];
    int tid = threadIdx.x;
    for (int idx = tid; idx < 4096; idx += 256) sW[idx] = W1[idx];
    __syncthreads();

    int j = tid & 63, slot = tid >> 6;   // 4 slots x 8 nodes = 32 / iter
    for (int base = blockIdx.x * 32; base < N; base += gridDim.x * 32) {
        __syncthreads();
        for (int idx = tid; idx < 2048; idx += 256) {
            int n = base + (idx >> 6);
            sx[idx] = (n < N) ? g_h[(size_t)n * 64 + (idx & 63)] : 0.f;
        }
        __syncthreads();
        float a[8];
        #pragma unroll
        for (int r = 0; r < 8; r++) a[r] = 0.f;
        const float* xs = &sx[slot * 512];
        #pragma unroll
        for (int k = 0; k < 64; k += 4) {
            float4 xv[8];
            #pragma unroll
            for (int r = 0; r < 8; r++) xv[r] = *(const float4*)&xs[r * 64 + k];
            #pragma unroll
            for (int kk = 0; kk < 4; kk++) {
                float w = sW[(k + kk) * 64 + j];
                #pragma unroll
                for (int r = 0; r < 8; r++) a[r] += (&xv[r].x)[kk] * w;
            }
        }
        int n0 = base + slot * 8;
        #pragma unroll
        for (int r = 0; r < 8; r++) {
            int n = n0 + r;
            if (n < N) g_hw[(size_t)n * 64 + j] = a[r] * g_dinv[n];
        }
    }
}

// ---------------------------------------------------------------- fused conv1-gather + conv2 GEMM
// Phase A: gather out1 tile (64 cols) into smem: out1 = relu(dinv[c]*(hws[c]+sum)+b1)
// Phase B: g_hw2 = dinv[n] * (out1 @ W2)
__global__ void k_conv2a(const float* __restrict__ W2, const float* __restrict__ b1, int N) {
    __shared__ float sW[64 * 32];
    __shared__ float sx[64 * 64];
    int tid = threadIdx.x;
    for (int idx = tid; idx < 2048; idx += 256) sW[idx] = W2[idx];

    int base = blockIdx.x * 64;

    // Phase A: 64 cols x 16 lanes = 1024 units, 4 per thread
    int ln = tid & 15;
    float4 bv = *(const float4*)&b1[ln * 4];
    #pragma unroll
    for (int rep = 0; rep < 4; rep++) {
        int cl = (tid >> 4) + rep * 16;      // 0..63
        int c = base + cl;
        float4 o = make_float4(0.f, 0.f, 0.f, 0.f);
        if (c < N) {
            int s = g_start[c], cnt = g_cnt[c];
            float4 acc = *(const float4*)&g_hw[(size_t)c * 64 + ln * 4];   // self term
            int r = (cnt > 0) ? __ldg(&g_elist[s]) : 0;
            for (int i = 0; i < cnt; i++) {
                int rn = (i + 1 < cnt) ? __ldg(&g_elist[s + i + 1]) : 0;
                float4 v = *(const float4*)&g_hw[(size_t)r * 64 + ln * 4];
                acc.x += v.x; acc.y += v.y; acc.z += v.z; acc.w += v.w;
                r = rn;
            }
            float dc = g_dinv[c];
            o.x = fmaxf(acc.x * dc + bv.x, 0.f);
            o.y = fmaxf(acc.y * dc + bv.y, 0.f);
            o.z = fmaxf(acc.z * dc + bv.z, 0.f);
            o.w = fmaxf(acc.w * dc + bv.w, 0.f);
        }
        *(float4*)&sx[cl * 64 + ln * 4] = o;
    }
    __syncthreads();

    // Phase B: GEMM, 8 slots x 8 nodes
    int j = tid & 31, slot = tid >> 5;
    float a[8];
    #pragma unroll
    for (int r = 0; r < 8; r++) a[r] = 0.f;
    const float* xs = &sx[slot * 512];
    #pragma unroll
    for (int k = 0; k < 64; k += 4) {
        float4 xv[8];
        #pragma unroll
        for (int r = 0; r < 8; r++) xv[r] = *(const float4*)&xs[r * 64 + k];
        #pragma unroll
        for (int kk = 0; kk < 4; kk++) {
            float w = sW[(k + kk) * 32 + j];
            #pragma unroll
            for (int r = 0; r < 8; r++) a[r] += (&xv[r].x)[kk] * w;
        }
    }
    int n0 = base + slot * 8;
    #pragma unroll
    for (int r = 0; r < 8; r++) {
        int n = n0 + r;
        if (n < N) g_hw2[(size_t)n * 32 + j] = a[r] * g_dinv[n];
    }
}

// ---------------------------------------------------------------- conv2 gather: z[c] = dinv[c]*(hw2s[c] + sum) + b2
__global__ void k_gather2(const float* __restrict__ b2, int N) {
    int g = blockIdx.x * blockDim.x + threadIdx.x;
    int c = g >> 3, ln = g & 7;
    if (c >= N) return;
    int s = g_start[c], cnt = g_cnt[c];
    float4 acc = *(const float4*)&g_hw2[(size_t)c * 32 + ln * 4];  // self term
    int r = (cnt > 0) ? __ldg(&g_elist[s]) : 0;
    for (int i = 0; i < cnt; i++) {
        int rn = (i + 1 < cnt) ? __ldg(&g_elist[s + i + 1]) : 0;
        float4 v = *(const float4*)&g_hw2[(size_t)r * 32 + ln * 4];
        acc.x += v.x; acc.y += v.y; acc.z += v.z; acc.w += v.w;
        r = rn;
    }
    float dc = g_dinv[c];
    float4 b = *(const float4*)&b2[ln * 4];
    float4 o;
    o.x = acc.x * dc + b.x;
    o.y = acc.y * dc + b.y;
    o.z = acc.z * dc + b.z;
    o.w = acc.w * dc + b.w;
    *(float4*)&g_z[(size_t)c * 32 + ln * 4] = o;
}

// ---------------------------------------------------------------- label-edge dot (8 threads/edge)
__global__ void k_dot(const int* __restrict__ eli, float* __restrict__ out, int EL) {
    int t = blockIdx.x * blockDim.x + threadIdx.x;
    int e = t >> 3, c = t & 7;
    if (e >= EL) return;
    int s = __ldg(&eli[e]);
    int d = __ldg(&eli[EL + e]);
    float4 a = *(const float4*)&g_z[(size_t)s * 32 + c * 4];
    float4 b = *(const float4*)&g_z[(size_t)d * 32 + c * 4];
    float p = a.x * b.x + a.y * b.y + a.z * b.z + a.w * b.w;
    p += __shfl_down_sync(0xffffffffu, p, 4, 8);
    p += __shfl_down_sync(0xffffffffu, p, 2, 8);
    p += __shfl_down_sync(0xffffffffu, p, 1, 8);
    if (c == 0) out[e] = p;
}

// ---------------------------------------------------------------- launch
extern "C" void kernel_launch(void* const* d_in, const int* in_sizes, int n_in,
                              void* d_out, int out_size) {
    const float* x   = (const float*)d_in[0];
    const int*   ei  = (const int*)  d_in[1];
    const int*   eli = (const int*)  d_in[2];
    const float* Wih = (const float*)d_in[3];
    // d_in[4] = W_hh: unused (h0 == 0 => W_hh @ h0 == 0)
    const float* bih = (const float*)d_in[5];
    const float* bhh = (const float*)d_in[6];
    const float* W1  = (const float*)d_in[7];
    const float* b1  = (const float*)d_in[8];
    const float* W2  = (const float*)d_in[9];
    const float* b2  = (const float*)d_in[10];
    float* out = (float*)d_out;

    int N  = in_sizes[0] / 64;
    int E  = in_sizes[1] / 2;
    int EL = in_sizes[2] / 2;

    const int LSTM_SMEM = (64 * LSTM_WS + 192 + 2048) * 4;  // 58112 B
    cudaFuncSetAttribute(k_lstm, cudaFuncAttributeMaxDynamicSharedMemorySize, LSTM_SMEM);
    (void)cudaGetLastError();  // never poison the capture stream

    int nb    = (N + 255) / 256;
    int nscan = (N + 1023) / 1024;

    // CSR build + norms (5 launches)
    k_zero <<<nb, 256>>>(N);
    k_hist <<<(E + 255) / 256, 256>>>(ei, E);
    k_scan1<<<nscan, 256>>>(N);
    k_scan3<<<nb, 256>>>(N);
    k_fill <<<(E + 255) / 256, 256>>>(ei, E);

    // Pipeline (k_lstm is launch index 5 -> ncu -s 5 captures it)
    k_lstm   <<<444, 256, LSTM_SMEM>>>(x, Wih, bih, bhh, N);
    k_gemm1  <<<592, 256>>>(W1, N);
    k_conv2a <<<(N + 63) / 64, 256>>>(W2, b1, N);
    k_gather2<<<(N * 8 + 255) / 256, 256>>>(b2, N);
    k_dot    <<<(EL * 8 + 255) / 256, 256>>>(eli, out, EL);
}